// round 5
// baseline (speedup 1.0000x reference)
#include <cuda_runtime.h>
#include <cuda_bf16.h>
#include <cstdint>

// Problem constants (RestGCNEqualHidden): N=50000, F=H=128, C=40, E=800000
#define MAXN 50016
#define MAXE 800000
#define FDIM 128
#define CDIM 40
#define SCAN_T 1024

// Scratch (device globals -- no allocation allowed)
__device__ int   g_is64;
__device__ int   g_src [MAXE];
__device__ int   g_dst [MAXE];
__device__ int   g_csr [MAXE];
__device__ int   g_deg [MAXN];
__device__ int   g_off [MAXN + 1];
__device__ int   g_cur [MAXN];
__device__ float g_dinv[MAXN];
__device__ __align__(16) float g_g1  [(size_t)MAXN * FDIM];  // (x@W1)*dinv[row]
__device__ __align__(16) float g_x1c [(size_t)MAXN * FDIM];  // relu(conv1)+x
__device__ __align__(16) float g_g2  [(size_t)MAXN * CDIM];  // (x1c@W2)*dinv[row]

// ---------------- dtype detect: int64 edges have zero high words ------------
__global__ void detect_kernel(const int* __restrict__ ei32) {
    if (threadIdx.x == 0 && blockIdx.x == 0) {
        int is64 = 1;
        for (int i = 1; i < 256; i += 2)
            if (ei32[i] != 0) { is64 = 0; break; }
        g_is64 = is64;
    }
}

// ---------------- convert edges to int32 + degree histogram -----------------
__global__ void convert_kernel(const void* __restrict__ ei, int E) {
    int i = blockIdx.x * blockDim.x + threadIdx.x;
    if (i >= E) return;
    int s, d;
    if (g_is64) {
        const long long* p = (const long long*)ei;
        s = (int)p[i];
        d = (int)p[(size_t)E + i];
    } else {
        const int* p = (const int*)ei;
        s = p[i];
        d = p[E + i];
    }
    g_src[i] = s;
    g_dst[i] = d;
    atomicAdd(&g_deg[d], 1);
}

// ---------------- one-block exclusive scan of degrees + dinv ----------------
__global__ void scan_kernel(int N) {
    __shared__ int part[SCAN_T];
    int t = threadIdx.x;
    int chunk = (N + SCAN_T - 1) / SCAN_T;
    int lo = t * chunk;
    int hi = min(lo + chunk, N);
    int s = 0;
    for (int i = lo; i < hi; i++) s += g_deg[i];
    part[t] = s;
    __syncthreads();
    for (int d = 1; d < SCAN_T; d <<= 1) {
        int v = (t >= d) ? part[t - d] : 0;
        __syncthreads();
        part[t] += v;
        __syncthreads();
    }
    int base = (t == 0) ? 0 : part[t - 1];
    for (int i = lo; i < hi; i++) {
        g_off[i] = base;
        g_cur[i] = base;
        g_dinv[i] = rsqrtf((float)g_deg[i] + 1.0f);   // +1 for self loop
        base += g_deg[i];
    }
    if (t == SCAN_T - 1) g_off[N] = base;
}

// ---------------- CSR fill: bucket src by dst -------------------------------
__global__ void fill_kernel(int E) {
    int i = blockIdx.x * blockDim.x + threadIdx.x;
    if (i >= E) return;
    int d = g_dst[i];
    int pos = atomicAdd(&g_cur[d], 1);
    g_csr[pos] = g_src[i];
}

// ---------------- GEMM1: g1 = (x @ W1) * dinv -------------------------------
// tile 64 rows x 128 cols, K=128 in one shot. 256 threads, each 8x4 outputs.
__global__ void gemm1_kernel(const float* __restrict__ x,
                             const float* __restrict__ W, int N) {
    extern __shared__ float sm[];
    float* sX = sm;               // 64 * 128
    float* sW = sm + 64 * 128;    // 128 * 128
    int tid  = threadIdx.x;
    int row0 = blockIdx.x * 64;

    const float4* W4 = (const float4*)W;
    float4* sW4 = (float4*)sW;
#pragma unroll
    for (int i = 0; i < 16; i++) sW4[tid + i * 256] = W4[tid + i * 256];

    const float4* X4 = (const float4*)x;
    float4* sX4 = (float4*)sX;
#pragma unroll
    for (int i = 0; i < 8; i++) {
        int f = tid + i * 256;           // [0, 2048)
        int r = f >> 5, c4 = f & 31;
        float4 v = make_float4(0.f, 0.f, 0.f, 0.f);
        if (row0 + r < N) v = X4[(size_t)(row0 + r) * 32 + c4];
        sX4[f] = v;
    }
    __syncthreads();

    int cg = tid & 31;   // 32 col-groups * 4 cols
    int rg = tid >> 5;   // 8 row-groups * 8 rows
    float acc[8][4] = {};
#pragma unroll 8
    for (int k = 0; k < 128; k++) {
        float4 wv = ((const float4*)(sW + k * 128))[cg];
        float xr[8];
#pragma unroll
        for (int i = 0; i < 8; i++) xr[i] = sX[(rg * 8 + i) * 128 + k];
#pragma unroll
        for (int i = 0; i < 8; i++) {
            acc[i][0] += xr[i] * wv.x;
            acc[i][1] += xr[i] * wv.y;
            acc[i][2] += xr[i] * wv.z;
            acc[i][3] += xr[i] * wv.w;
        }
    }
#pragma unroll
    for (int i = 0; i < 8; i++) {
        int r = row0 + rg * 8 + i;
        if (r < N) {
            float dv = g_dinv[r];
            float4 o = make_float4(acc[i][0] * dv, acc[i][1] * dv,
                                   acc[i][2] * dv, acc[i][3] * dv);
            ((float4*)g_g1)[(size_t)r * 32 + cg] = o;
        }
    }
}

// ------- gather layer 1 + fused epilogue: x1c = relu(agg*dinv+b1)+x ---------
// one warp per node; lane owns a float4 (128 floats/node)
__global__ void gather1_kernel(const float4* __restrict__ x,
                               const float* __restrict__ b1, int N) {
    int node = blockIdx.x * 8 + (threadIdx.x >> 5);
    int lane = threadIdx.x & 31;
    if (node >= N) return;
    const float4* G = (const float4*)g_g1;
    float4 acc = G[(size_t)node * 32 + lane];   // self loop term
    int e  = g_off[node];
    int e1 = g_off[node + 1];
    for (; e + 2 <= e1; e += 2) {
        int s0 = g_csr[e], s1 = g_csr[e + 1];
        float4 v0 = G[(size_t)s0 * 32 + lane];
        float4 v1 = G[(size_t)s1 * 32 + lane];
        acc.x += v0.x + v1.x;
        acc.y += v0.y + v1.y;
        acc.z += v0.z + v1.z;
        acc.w += v0.w + v1.w;
    }
    if (e < e1) {
        int s = g_csr[e];
        float4 v = G[(size_t)s * 32 + lane];
        acc.x += v.x; acc.y += v.y; acc.z += v.z; acc.w += v.w;
    }
    float dv = g_dinv[node];
    float4 b  = ((const float4*)b1)[lane];
    float4 xv = x[(size_t)node * 32 + lane];
    float4 o;
    o.x = fmaxf(fmaf(acc.x, dv, b.x), 0.f) + xv.x;
    o.y = fmaxf(fmaf(acc.y, dv, b.y), 0.f) + xv.y;
    o.z = fmaxf(fmaf(acc.z, dv, b.z), 0.f) + xv.z;
    o.w = fmaxf(fmaf(acc.w, dv, b.w), 0.f) + xv.w;
    ((float4*)g_x1c)[(size_t)node * 32 + lane] = o;
}

// ---------------- GEMM2: g2 = (x1c @ W2) * dinv -----------------------------
// tile 128 rows x 40 cols, 256 threads each 4x5 outputs. sX padded to 132.
__global__ void gemm2_kernel(const float* __restrict__ W, int N) {
    extern __shared__ float sm[];
    float* sX = sm;                 // 128 * 132
    float* sW = sm + 128 * 132;     // 128 * 40
    int tid  = threadIdx.x;
    int row0 = blockIdx.x * 128;

#pragma unroll
    for (int i = 0; i < 5; i++)
        ((float4*)sW)[tid + i * 256] = ((const float4*)W)[tid + i * 256];

#pragma unroll
    for (int i = 0; i < 16; i++) {
        int f = tid + i * 256;          // [0, 4096)
        int r = f >> 5, c4 = f & 31;
        float4 v = make_float4(0.f, 0.f, 0.f, 0.f);
        if (row0 + r < N) v = ((const float4*)g_x1c)[(size_t)(row0 + r) * 32 + c4];
        *((float4*)(sX + r * 132 + c4 * 4)) = v;
    }
    __syncthreads();

    int cg = tid & 7;    // 8 col-groups * 5 cols
    int rg = tid >> 3;   // 32 row-groups * 4 rows
    float acc[4][5] = {};
#pragma unroll 4
    for (int k = 0; k < 128; k++) {
        float wv[5];
#pragma unroll
        for (int j = 0; j < 5; j++) wv[j] = sW[k * 40 + cg * 5 + j];
#pragma unroll
        for (int i = 0; i < 4; i++) {
            float xv = sX[(rg * 4 + i) * 132 + k];
#pragma unroll
            for (int j = 0; j < 5; j++) acc[i][j] += xv * wv[j];
        }
    }
#pragma unroll
    for (int i = 0; i < 4; i++) {
        int r = row0 + rg * 4 + i;
        if (r < N) {
            float dv = g_dinv[r];
#pragma unroll
            for (int j = 0; j < 5; j++)
                g_g2[(size_t)r * 40 + cg * 5 + j] = acc[i][j] * dv;
        }
    }
}

// ------- gather layer 2 + fused epilogue: y = agg*dinv + b2 -----------------
// one warp per node; lanes 0-9 each own a float4 (40 floats/node)
__global__ void gather2_kernel(const float* __restrict__ b2,
                               float4* __restrict__ out, int N) {
    int node = blockIdx.x * 8 + (threadIdx.x >> 5);
    int lane = threadIdx.x & 31;
    if (node >= N || lane >= 10) return;
    const float4* G = (const float4*)g_g2;
    float4 acc = G[(size_t)node * 10 + lane];   // self loop term
    int e  = g_off[node];
    int e1 = g_off[node + 1];
    for (; e + 2 <= e1; e += 2) {
        int s0 = g_csr[e], s1 = g_csr[e + 1];
        float4 v0 = G[(size_t)s0 * 10 + lane];
        float4 v1 = G[(size_t)s1 * 10 + lane];
        acc.x += v0.x + v1.x;
        acc.y += v0.y + v1.y;
        acc.z += v0.z + v1.z;
        acc.w += v0.w + v1.w;
    }
    if (e < e1) {
        int s = g_csr[e];
        float4 v = G[(size_t)s * 10 + lane];
        acc.x += v.x; acc.y += v.y; acc.z += v.z; acc.w += v.w;
    }
    float dv = g_dinv[node];
    float4 b = ((const float4*)b2)[lane];
    float4 o;
    o.x = fmaf(acc.x, dv, b.x);
    o.y = fmaf(acc.y, dv, b.y);
    o.z = fmaf(acc.z, dv, b.z);
    o.w = fmaf(acc.w, dv, b.w);
    out[(size_t)node * 10 + lane] = o;
}

extern "C" void kernel_launch(void* const* d_in, const int* in_sizes, int n_in,
                              void* d_out, int out_size) {
    const float* x  = (const float*)d_in[0];
    const void*  ei = (const void*)d_in[1];
    const float* W1 = (const float*)d_in[2];
    const float* b1 = (const float*)d_in[3];
    const float* W2 = (const float*)d_in[4];
    const float* b2 = (const float*)d_in[5];

    int N = in_sizes[0] / FDIM;     // 50000
    int E = in_sizes[1] / 2;        // 800000

    // zero degree counters
    void* degp = nullptr;
    cudaGetSymbolAddress(&degp, g_deg);
    cudaMemsetAsync(degp, 0, (size_t)N * sizeof(int));

    int smem1 = (64 * 128 + 128 * 128) * sizeof(float);      // 96 KB
    int smem2 = (128 * 132 + 128 * 40) * sizeof(float);      // ~86 KB
    cudaFuncSetAttribute(gemm1_kernel, cudaFuncAttributeMaxDynamicSharedMemorySize, smem1);
    cudaFuncSetAttribute(gemm2_kernel, cudaFuncAttributeMaxDynamicSharedMemorySize, smem2);

    detect_kernel<<<1, 32>>>((const int*)ei);
    convert_kernel<<<(E + 255) / 256, 256>>>(ei, E);
    scan_kernel<<<1, SCAN_T>>>(N);
    fill_kernel<<<(E + 255) / 256, 256>>>(E);

    gemm1_kernel<<<(N + 63) / 64, 256, smem1>>>(x, W1, N);
    gather1_kernel<<<(N + 7) / 8, 256>>>((const float4*)x, b1, N);

    gemm2_kernel<<<(N + 127) / 128, 256, smem2>>>(W2, N);
    gather2_kernel<<<(N + 7) / 8, 256>>>(b2, (float4*)d_out, N);
}

// round 6
// speedup vs baseline: 1.2812x; 1.2812x over previous
#include <cuda_runtime.h>
#include <cuda_bf16.h>
#include <cstdint>

// Problem constants (RestGCNEqualHidden): N=50000, F=H=128, C=40, E=800000
#define MAXN 50016
#define MAXE 800000
#define FDIM 128
#define CDIM 40

// Scratch (device globals -- no allocation allowed)
__device__ int   g_is64;
__device__ int   g_src [MAXE];
__device__ int   g_dst [MAXE];
__device__ int   g_deg [MAXN];
__device__ float g_dinv[MAXN];
__device__ __align__(16) float g_g1  [(size_t)MAXN * FDIM];  // (x@W1)*dinv
__device__ __align__(16) float g_agg1[(size_t)MAXN * FDIM];  // scatter target
__device__ __align__(16) float g_g2  [(size_t)MAXN * CDIM];
__device__ __align__(16) float g_agg2[(size_t)MAXN * CDIM];

__device__ __forceinline__ void red_add_v4(float* addr, float4 v) {
    asm volatile("red.global.add.v4.f32 [%0], {%1,%2,%3,%4};"
                 :: "l"(addr), "f"(v.x), "f"(v.y), "f"(v.z), "f"(v.w)
                 : "memory");
}

__device__ __forceinline__ uint32_t f2tf(float f) {
    uint32_t u;
    asm("cvt.rna.tf32.f32 %0, %1;" : "=r"(u) : "f"(f));
    return u;
}

// ---------------- dtype detect: int64 edges have zero high words ------------
__global__ void detect_kernel(const int* __restrict__ ei32) {
    if (threadIdx.x == 0 && blockIdx.x == 0) {
        int is64 = 1;
        for (int i = 1; i < 256; i += 2)
            if (ei32[i] != 0) { is64 = 0; break; }
        g_is64 = is64;
    }
}

// ---------------- convert edges to int32 + degree histogram -----------------
__global__ void convert_kernel(const void* __restrict__ ei, int E) {
    int i = blockIdx.x * blockDim.x + threadIdx.x;
    if (i >= E) return;
    int s, d;
    if (g_is64) {
        const long long* p = (const long long*)ei;
        s = (int)p[i];
        d = (int)p[(size_t)E + i];
    } else {
        const int* p = (const int*)ei;
        s = p[i];
        d = p[E + i];
    }
    g_src[i] = s;
    g_dst[i] = d;
    atomicAdd(&g_deg[d], 1);
}

__global__ void dinv_kernel(int N) {
    int i = blockIdx.x * blockDim.x + threadIdx.x;
    if (i < N) g_dinv[i] = rsqrtf((float)g_deg[i] + 1.0f);  // +1 self loop
}

// ------- GEMM1 (tf32 mma.sync): g1 = agg1 = (x @ W1) * dinv -----------------
// 256 threads = 8 warps (2x4), block tile 128x128, K=128 single shot.
// Warp tile 64x32; per warp 4 m-subtiles x 4 n-subtiles of m16n8k8.
__global__ void gemm1_kernel(const float* __restrict__ x,
                             const float* __restrict__ W, int N) {
    extern __shared__ float sm[];
    float* sX = sm;                  // 128 x 132 (pad 4)
    float* sW = sm + 128 * 132;      // 128 x 132
    int tid  = threadIdx.x;
    int row0 = blockIdx.x * 128;

    // load W tile [128 x 128] (row-major, k rows, n cols)
#pragma unroll
    for (int i = 0; i < 16; i++) {
        int f = tid + i * 256;       // [0, 4096)
        int r = f >> 5, c4 = f & 31;
        float4 v = ((const float4*)W)[(size_t)r * 32 + c4];
        *((float4*)(sW + r * 132 + c4 * 4)) = v;
    }
    // load x tile [128 x 128]
#pragma unroll
    for (int i = 0; i < 16; i++) {
        int f = tid + i * 256;
        int r = f >> 5, c4 = f & 31;
        float4 v = make_float4(0.f, 0.f, 0.f, 0.f);
        if (row0 + r < N) v = ((const float4*)x)[(size_t)(row0 + r) * 32 + c4];
        *((float4*)(sX + r * 132 + c4 * 4)) = v;
    }
    __syncthreads();

    int warp  = tid >> 5;
    int lane  = tid & 31;
    int warpM = warp >> 2;           // 0..1  (64 rows each)
    int warpN = warp & 3;            // 0..3  (32 cols each)
    int g   = lane >> 2;             // 0..7
    int tig = lane & 3;              // 0..3

    float acc[4][4][4];
#pragma unroll
    for (int mi = 0; mi < 4; mi++)
#pragma unroll
        for (int ni = 0; ni < 4; ni++)
#pragma unroll
            for (int c = 0; c < 4; c++) acc[mi][ni][c] = 0.f;

#pragma unroll
    for (int k0 = 0; k0 < 128; k0 += 8) {
        uint32_t a[4][4];
#pragma unroll
        for (int mi = 0; mi < 4; mi++) {
            int r = warpM * 64 + mi * 16 + g;
            a[mi][0] = f2tf(sX[(r)     * 132 + k0 + tig]);
            a[mi][1] = f2tf(sX[(r + 8) * 132 + k0 + tig]);
            a[mi][2] = f2tf(sX[(r)     * 132 + k0 + 4 + tig]);
            a[mi][3] = f2tf(sX[(r + 8) * 132 + k0 + 4 + tig]);
        }
        uint32_t b[4][2];
#pragma unroll
        for (int ni = 0; ni < 4; ni++) {
            int col = warpN * 32 + ni * 8 + g;
            b[ni][0] = f2tf(sW[(k0 + tig)     * 132 + col]);
            b[ni][1] = f2tf(sW[(k0 + 4 + tig) * 132 + col]);
        }
#pragma unroll
        for (int mi = 0; mi < 4; mi++)
#pragma unroll
            for (int ni = 0; ni < 4; ni++)
                asm volatile(
                    "mma.sync.aligned.m16n8k8.row.col.f32.tf32.tf32.f32 "
                    "{%0,%1,%2,%3},{%4,%5,%6,%7},{%8,%9},{%0,%1,%2,%3};"
                    : "+f"(acc[mi][ni][0]), "+f"(acc[mi][ni][1]),
                      "+f"(acc[mi][ni][2]), "+f"(acc[mi][ni][3])
                    : "r"(a[mi][0]), "r"(a[mi][1]), "r"(a[mi][2]), "r"(a[mi][3]),
                      "r"(b[ni][0]), "r"(b[ni][1]));
    }

    // epilogue: scale by dinv[row], write g1 and agg1 (self-loop init)
#pragma unroll
    for (int mi = 0; mi < 4; mi++) {
        int r0 = row0 + warpM * 64 + mi * 16 + g;
        int r1 = r0 + 8;
        float dv0 = (r0 < N) ? g_dinv[r0] : 0.f;
        float dv1 = (r1 < N) ? g_dinv[r1] : 0.f;
#pragma unroll
        for (int ni = 0; ni < 4; ni++) {
            int col = warpN * 32 + ni * 8 + 2 * tig;
            if (r0 < N) {
                float2 o = make_float2(acc[mi][ni][0] * dv0, acc[mi][ni][1] * dv0);
                *((float2*)(g_g1   + (size_t)r0 * 128 + col)) = o;
                *((float2*)(g_agg1 + (size_t)r0 * 128 + col)) = o;
            }
            if (r1 < N) {
                float2 o = make_float2(acc[mi][ni][2] * dv1, acc[mi][ni][3] * dv1);
                *((float2*)(g_g1   + (size_t)r1 * 128 + col)) = o;
                *((float2*)(g_agg1 + (size_t)r1 * 128 + col)) = o;
            }
        }
    }
}

// ---------------- edge scatter layer 1: agg1[dst] += g1[src] ----------------
__global__ void scatter1_kernel(int E) {
    int w = blockIdx.x * 8 + (threadIdx.x >> 5);
    int lane = threadIdx.x & 31;
    if (w >= E) return;
    int s = g_src[w];
    int d = g_dst[w];
    float4 v = ((const float4*)g_g1)[(size_t)s * 32 + lane];
    red_add_v4(&g_agg1[(size_t)d * FDIM + lane * 4], v);
}

// ---- GEMM2 with fused epilogue-of-layer1 in the load stage -----------------
// x1c = relu(agg1*dinv + b1) + x computed on the fly into smem, then
// g2 = agg2 = (x1c @ W2) * dinv. tile 128 rows x 40 cols, 256 thr, 4x5 out.
__global__ void gemm2_kernel(const float* __restrict__ W,
                             const float4* __restrict__ x,
                             const float* __restrict__ b1, int N) {
    extern __shared__ float sm[];
    float* sX = sm;                 // 128 * 132
    float* sW = sm + 128 * 132;     // 128 * 40
    int tid  = threadIdx.x;
    int row0 = blockIdx.x * 128;

#pragma unroll
    for (int i = 0; i < 5; i++)
        ((float4*)sW)[tid + i * 256] = ((const float4*)W)[tid + i * 256];

#pragma unroll
    for (int i = 0; i < 16; i++) {
        int f = tid + i * 256;          // [0, 4096)
        int r = f >> 5, c4 = f & 31;
        int row = row0 + r;
        float4 o = make_float4(0.f, 0.f, 0.f, 0.f);
        if (row < N) {
            float dv  = g_dinv[row];
            float4 a  = ((const float4*)g_agg1)[(size_t)row * 32 + c4];
            float4 xv = x[(size_t)row * 32 + c4];
            float4 b  = ((const float4*)b1)[c4];
            o.x = fmaxf(fmaf(a.x, dv, b.x), 0.f) + xv.x;
            o.y = fmaxf(fmaf(a.y, dv, b.y), 0.f) + xv.y;
            o.z = fmaxf(fmaf(a.z, dv, b.z), 0.f) + xv.z;
            o.w = fmaxf(fmaf(a.w, dv, b.w), 0.f) + xv.w;
        }
        *((float4*)(sX + r * 132 + c4 * 4)) = o;
    }
    __syncthreads();

    int cg = tid & 7;    // 8 col-groups * 5 cols
    int rg = tid >> 3;   // 32 row-groups * 4 rows
    float acc[4][5] = {};
#pragma unroll 4
    for (int k = 0; k < 128; k++) {
        float wv[5];
#pragma unroll
        for (int j = 0; j < 5; j++) wv[j] = sW[k * 40 + cg * 5 + j];
#pragma unroll
        for (int i = 0; i < 4; i++) {
            float xv = sX[(rg * 4 + i) * 132 + k];
#pragma unroll
            for (int j = 0; j < 5; j++) acc[i][j] += xv * wv[j];
        }
    }
#pragma unroll
    for (int i = 0; i < 4; i++) {
        int r = row0 + rg * 4 + i;
        if (r < N) {
            float dv = g_dinv[r];
#pragma unroll
            for (int j = 0; j < 5; j++) {
                float o = acc[i][j] * dv;
                g_g2  [(size_t)r * 40 + cg * 5 + j] = o;
                g_agg2[(size_t)r * 40 + cg * 5 + j] = o;
            }
        }
    }
}

// ---------------- edge scatter layer 2: agg2[dst] += g2[src] ----------------
__global__ void scatter2_kernel(int E) {
    int idx = blockIdx.x * blockDim.x + threadIdx.x;
    if (idx >= E * 10) return;
    int e = idx / 10, c = idx - e * 10;
    int s = g_src[e];
    int d = g_dst[e];
    float4 v = ((const float4*)g_g2)[(size_t)s * 10 + c];
    red_add_v4(&g_agg2[(size_t)d * CDIM + c * 4], v);
}

// ---------------- final: y = agg2 * dinv + b2 ----------------
__global__ void final_kernel(const float* __restrict__ b2,
                             float4* __restrict__ out, int N) {
    int idx = blockIdx.x * blockDim.x + threadIdx.x;
    if (idx >= N * 10) return;
    int r = idx / 10, c = idx - r * 10;
    float dv = g_dinv[r];
    float4 a = ((const float4*)g_agg2)[idx];
    float4 b = ((const float4*)b2)[c];
    float4 o;
    o.x = fmaf(a.x, dv, b.x);
    o.y = fmaf(a.y, dv, b.y);
    o.z = fmaf(a.z, dv, b.z);
    o.w = fmaf(a.w, dv, b.w);
    out[idx] = o;
}

extern "C" void kernel_launch(void* const* d_in, const int* in_sizes, int n_in,
                              void* d_out, int out_size) {
    const float* x  = (const float*)d_in[0];
    const void*  ei = (const void*)d_in[1];
    const float* W1 = (const float*)d_in[2];
    const float* b1 = (const float*)d_in[3];
    const float* W2 = (const float*)d_in[4];
    const float* b2 = (const float*)d_in[5];

    int N = in_sizes[0] / FDIM;     // 50000
    int E = in_sizes[1] / 2;        // 800000

    void* degp = nullptr;
    cudaGetSymbolAddress(&degp, g_deg);
    cudaMemsetAsync(degp, 0, (size_t)N * sizeof(int));

    int smem1 = (128 * 132 + 128 * 132) * sizeof(float);     // ~132 KB
    int smem2 = (128 * 132 + 128 * 40) * sizeof(float);      // ~86 KB
    cudaFuncSetAttribute(gemm1_kernel, cudaFuncAttributeMaxDynamicSharedMemorySize, smem1);
    cudaFuncSetAttribute(gemm2_kernel, cudaFuncAttributeMaxDynamicSharedMemorySize, smem2);

    detect_kernel<<<1, 32>>>((const int*)ei);
    convert_kernel<<<(E + 255) / 256, 256>>>(ei, E);
    dinv_kernel<<<(N + 255) / 256, 256>>>(N);

    gemm1_kernel<<<(N + 127) / 128, 256, smem1>>>(x, W1, N);
    scatter1_kernel<<<(E + 7) / 8, 256>>>(E);

    gemm2_kernel<<<(N + 127) / 128, 256, smem2>>>(W2, (const float4*)x, b1, N);
    scatter2_kernel<<<(E * 10 + 255) / 256, 256>>>(E);
    final_kernel<<<(N * 10 + 255) / 256, 256>>>(b2, (float4*)d_out, N);
}

// round 7
// speedup vs baseline: 1.3769x; 1.0747x over previous
#include <cuda_runtime.h>
#include <cuda_bf16.h>
#include <cstdint>

// Problem constants (RestGCNEqualHidden): N=50000, F=H=128, C=40, E=800000
#define MAXN 50016
#define MAXE 800000
#define FDIM 128
#define CDIM 40

// Scratch (device globals -- no allocation allowed)
__device__ int   g_is64;
__device__ int   g_src [MAXE];
__device__ int   g_dst [MAXE];
__device__ int   g_deg [MAXN];
__device__ float g_dinv[MAXN];
__device__ __align__(16) float g_g1  [(size_t)MAXN * FDIM];  // (x@W1)*dinv
__device__ __align__(16) float g_agg1[(size_t)MAXN * FDIM];  // scatter target
__device__ __align__(16) float g_g2  [(size_t)MAXN * CDIM];
__device__ __align__(16) float g_agg2[(size_t)MAXN * CDIM];

__device__ __forceinline__ void red_add_v4(float* addr, float4 v) {
    asm volatile("red.global.add.v4.f32 [%0], {%1,%2,%3,%4};"
                 :: "l"(addr), "f"(v.x), "f"(v.y), "f"(v.z), "f"(v.w)
                 : "memory");
}

__device__ __forceinline__ uint32_t f2tf(float f) {
    uint32_t u;
    asm("cvt.rna.tf32.f32 %0, %1;" : "=r"(u) : "f"(f));
    return u;
}

// ---------------- dtype detect: int64 edges have zero high words ------------
__global__ void detect_kernel(const int* __restrict__ ei32) {
    if (threadIdx.x == 0 && blockIdx.x == 0) {
        int is64 = 1;
        for (int i = 1; i < 256; i += 2)
            if (ei32[i] != 0) { is64 = 0; break; }
        g_is64 = is64;
    }
}

// ---------------- convert edges to int32 + degree histogram -----------------
__global__ void convert_kernel(const void* __restrict__ ei, int E) {
    int i = blockIdx.x * blockDim.x + threadIdx.x;
    if (i >= E) return;
    int s, d;
    if (g_is64) {
        const long long* p = (const long long*)ei;
        s = (int)p[i];
        d = (int)p[(size_t)E + i];
    } else {
        const int* p = (const int*)ei;
        s = p[i];
        d = p[E + i];
    }
    g_src[i] = s;
    g_dst[i] = d;
    atomicAdd(&g_deg[d], 1);
}

__global__ void dinv_kernel(int N) {
    int i = blockIdx.x * blockDim.x + threadIdx.x;
    if (i < N) g_dinv[i] = rsqrtf((float)g_deg[i] + 1.0f);  // +1 self loop
}

// ------- GEMM1 (tf32 mma.sync): g1 = agg1 = (x @ W1) * dinv -----------------
// 256 threads = 8 warps (2x4), block tile 128x128, K split into 2 chunks of 64
// so smem fits 2 CTAs/SM. Warp tile 64x32 = 4x4 m16n8k8 subtiles.
#define SXP 68     // sX row stride (pad 4)
#define SWP 136    // sW row stride (pad 8 -> conflict-free B lds)
__global__ __launch_bounds__(256, 2)
void gemm1_kernel(const float* __restrict__ x,
                  const float* __restrict__ W, int N) {
    extern __shared__ float sm[];
    float* sX = sm;                 // 128 x SXP
    float* sW = sm + 128 * SXP;     // 64 x SWP
    int tid  = threadIdx.x;
    int row0 = blockIdx.x * 128;

    int warp  = tid >> 5;
    int lane  = tid & 31;
    int warpM = warp >> 2;           // 0..1  (64 rows each)
    int warpN = warp & 3;            // 0..3  (32 cols each)
    int g   = lane >> 2;             // 0..7
    int tig = lane & 3;              // 0..3

    float acc[4][4][4];
#pragma unroll
    for (int mi = 0; mi < 4; mi++)
#pragma unroll
        for (int ni = 0; ni < 4; ni++)
#pragma unroll
            for (int c = 0; c < 4; c++) acc[mi][ni][c] = 0.f;

    for (int chunk = 0; chunk < 2; chunk++) {
        int kbase = chunk * 64;
        // load W rows [kbase, kbase+64) x 128 cols
#pragma unroll
        for (int i = 0; i < 8; i++) {
            int f = tid + i * 256;          // [0, 2048)
            int kr = f >> 5, c4 = f & 31;
            float4 v = ((const float4*)W)[(size_t)(kbase + kr) * 32 + c4];
            *((float4*)(sW + kr * SWP + c4 * 4)) = v;
        }
        // load x rows x cols [kbase, kbase+64)
#pragma unroll
        for (int i = 0; i < 8; i++) {
            int f = tid + i * 256;          // [0, 2048)
            int r = f >> 4, c4 = f & 15;    // 16 float4 per row
            float4 v = make_float4(0.f, 0.f, 0.f, 0.f);
            if (row0 + r < N)
                v = ((const float4*)x)[(size_t)(row0 + r) * 32 + (kbase >> 2) + c4];
            *((float4*)(sX + r * SXP + c4 * 4)) = v;
        }
        __syncthreads();

#pragma unroll
        for (int k0 = 0; k0 < 64; k0 += 8) {
            uint32_t a[4][4];
#pragma unroll
            for (int mi = 0; mi < 4; mi++) {
                int r = warpM * 64 + mi * 16 + g;
                a[mi][0] = f2tf(sX[(r)     * SXP + k0 + tig]);
                a[mi][1] = f2tf(sX[(r + 8) * SXP + k0 + tig]);
                a[mi][2] = f2tf(sX[(r)     * SXP + k0 + 4 + tig]);
                a[mi][3] = f2tf(sX[(r + 8) * SXP + k0 + 4 + tig]);
            }
            uint32_t b[4][2];
#pragma unroll
            for (int ni = 0; ni < 4; ni++) {
                int col = warpN * 32 + ni * 8 + g;
                b[ni][0] = f2tf(sW[(k0 + tig)     * SWP + col]);
                b[ni][1] = f2tf(sW[(k0 + 4 + tig) * SWP + col]);
            }
#pragma unroll
            for (int mi = 0; mi < 4; mi++)
#pragma unroll
                for (int ni = 0; ni < 4; ni++)
                    asm volatile(
                        "mma.sync.aligned.m16n8k8.row.col.f32.tf32.tf32.f32 "
                        "{%0,%1,%2,%3},{%4,%5,%6,%7},{%8,%9},{%0,%1,%2,%3};"
                        : "+f"(acc[mi][ni][0]), "+f"(acc[mi][ni][1]),
                          "+f"(acc[mi][ni][2]), "+f"(acc[mi][ni][3])
                        : "r"(a[mi][0]), "r"(a[mi][1]), "r"(a[mi][2]), "r"(a[mi][3]),
                          "r"(b[ni][0]), "r"(b[ni][1]));
        }
        __syncthreads();
    }

    // epilogue: scale by dinv[row], write g1 and agg1 (self-loop init)
#pragma unroll
    for (int mi = 0; mi < 4; mi++) {
        int r0 = row0 + warpM * 64 + mi * 16 + g;
        int r1 = r0 + 8;
        float dv0 = (r0 < N) ? g_dinv[r0] : 0.f;
        float dv1 = (r1 < N) ? g_dinv[r1] : 0.f;
#pragma unroll
        for (int ni = 0; ni < 4; ni++) {
            int col = warpN * 32 + ni * 8 + 2 * tig;
            if (r0 < N) {
                float2 o = make_float2(acc[mi][ni][0] * dv0, acc[mi][ni][1] * dv0);
                *((float2*)(g_g1   + (size_t)r0 * 128 + col)) = o;
                *((float2*)(g_agg1 + (size_t)r0 * 128 + col)) = o;
            }
            if (r1 < N) {
                float2 o = make_float2(acc[mi][ni][2] * dv1, acc[mi][ni][3] * dv1);
                *((float2*)(g_g1   + (size_t)r1 * 128 + col)) = o;
                *((float2*)(g_agg1 + (size_t)r1 * 128 + col)) = o;
            }
        }
    }
}

// ---------------- edge scatter layer 1: agg1[dst] += g1[src] ----------------
__global__ void scatter1_kernel(int E) {
    int w = blockIdx.x * 8 + (threadIdx.x >> 5);
    int lane = threadIdx.x & 31;
    if (w >= E) return;
    int s = g_src[w];
    int d = g_dst[w];
    float4 v = ((const float4*)g_g1)[(size_t)s * 32 + lane];
    red_add_v4(&g_agg1[(size_t)d * FDIM + lane * 4], v);
}

// ---- GEMM2 (tf32 mma) with fused layer-1 epilogue in the load stage --------
// x1c = relu(agg1*dinv + b1) + x computed on the fly into smem, then
// g2 = agg2 = (x1c @ W2) * dinv. Block 128 rows x 40 cols, warp = 16 rows.
#define SX2P 132   // sX row stride
#define SW2P 44    // sW row stride
__global__ __launch_bounds__(256, 2)
void gemm2_kernel(const float* __restrict__ W,
                  const float4* __restrict__ x,
                  const float* __restrict__ b1, int N) {
    extern __shared__ float sm[];
    float* sX = sm;                  // 128 x SX2P
    float* sW = sm + 128 * SX2P;     // 128 x SW2P
    int tid  = threadIdx.x;
    int row0 = blockIdx.x * 128;

    // load W2 [128 x 40]
#pragma unroll
    for (int i = 0; i < 5; i++) {
        int f = tid + i * 256;           // [0, 1280)
        int kr = f / 10, c4 = f - kr * 10;
        float4 v = ((const float4*)W)[(size_t)kr * 10 + c4];
        *((float4*)(sW + kr * SW2P + c4 * 4)) = v;
    }
    // fused load: x1c = relu(agg1*dinv + b1) + x
#pragma unroll
    for (int i = 0; i < 16; i++) {
        int f = tid + i * 256;          // [0, 4096)
        int r = f >> 5, c4 = f & 31;
        int row = row0 + r;
        float4 o = make_float4(0.f, 0.f, 0.f, 0.f);
        if (row < N) {
            float dv  = g_dinv[row];
            float4 a  = ((const float4*)g_agg1)[(size_t)row * 32 + c4];
            float4 xv = x[(size_t)row * 32 + c4];
            float4 b  = ((const float4*)b1)[c4];
            o.x = fmaxf(fmaf(a.x, dv, b.x), 0.f) + xv.x;
            o.y = fmaxf(fmaf(a.y, dv, b.y), 0.f) + xv.y;
            o.z = fmaxf(fmaf(a.z, dv, b.z), 0.f) + xv.z;
            o.w = fmaxf(fmaf(a.w, dv, b.w), 0.f) + xv.w;
        }
        *((float4*)(sX + r * SX2P + c4 * 4)) = o;
    }
    __syncthreads();

    int warp = tid >> 5;        // 0..7, each owns 16 rows
    int lane = tid & 31;
    int g   = lane >> 2;        // 0..7
    int tig = lane & 3;         // 0..3

    float acc[5][4];
#pragma unroll
    for (int ni = 0; ni < 5; ni++)
#pragma unroll
        for (int c = 0; c < 4; c++) acc[ni][c] = 0.f;

#pragma unroll
    for (int k0 = 0; k0 < 128; k0 += 8) {
        int r = warp * 16 + g;
        uint32_t a0 = f2tf(sX[(r)     * SX2P + k0 + tig]);
        uint32_t a1 = f2tf(sX[(r + 8) * SX2P + k0 + tig]);
        uint32_t a2 = f2tf(sX[(r)     * SX2P + k0 + 4 + tig]);
        uint32_t a3 = f2tf(sX[(r + 8) * SX2P + k0 + 4 + tig]);
        uint32_t b[5][2];
#pragma unroll
        for (int ni = 0; ni < 5; ni++) {
            int col = ni * 8 + g;
            b[ni][0] = f2tf(sW[(k0 + tig)     * SW2P + col]);
            b[ni][1] = f2tf(sW[(k0 + 4 + tig) * SW2P + col]);
        }
#pragma unroll
        for (int ni = 0; ni < 5; ni++)
            asm volatile(
                "mma.sync.aligned.m16n8k8.row.col.f32.tf32.tf32.f32 "
                "{%0,%1,%2,%3},{%4,%5,%6,%7},{%8,%9},{%0,%1,%2,%3};"
                : "+f"(acc[ni][0]), "+f"(acc[ni][1]),
                  "+f"(acc[ni][2]), "+f"(acc[ni][3])
                : "r"(a0), "r"(a1), "r"(a2), "r"(a3),
                  "r"(b[ni][0]), "r"(b[ni][1]));
    }

    // epilogue: scale by dinv[row], write g2 and agg2 (self-loop init)
    {
        int r0 = row0 + warp * 16 + g;
        int r1 = r0 + 8;
        float dv0 = (r0 < N) ? g_dinv[r0] : 0.f;
        float dv1 = (r1 < N) ? g_dinv[r1] : 0.f;
#pragma unroll
        for (int ni = 0; ni < 5; ni++) {
            int col = ni * 8 + 2 * tig;
            if (r0 < N) {
                float2 o = make_float2(acc[ni][0] * dv0, acc[ni][1] * dv0);
                *((float2*)(g_g2   + (size_t)r0 * 40 + col)) = o;
                *((float2*)(g_agg2 + (size_t)r0 * 40 + col)) = o;
            }
            if (r1 < N) {
                float2 o = make_float2(acc[ni][2] * dv1, acc[ni][3] * dv1);
                *((float2*)(g_g2   + (size_t)r1 * 40 + col)) = o;
                *((float2*)(g_agg2 + (size_t)r1 * 40 + col)) = o;
            }
        }
    }
}

// ---------------- edge scatter layer 2: agg2[dst] += g2[src] ----------------
__global__ void scatter2_kernel(int E) {
    int idx = blockIdx.x * blockDim.x + threadIdx.x;
    if (idx >= E * 10) return;
    int e = idx / 10, c = idx - e * 10;
    int s = g_src[e];
    int d = g_dst[e];
    float4 v = ((const float4*)g_g2)[(size_t)s * 10 + c];
    red_add_v4(&g_agg2[(size_t)d * CDIM + c * 4], v);
}

// ---------------- final: y = agg2 * dinv + b2 ----------------
__global__ void final_kernel(const float* __restrict__ b2,
                             float4* __restrict__ out, int N) {
    int idx = blockIdx.x * blockDim.x + threadIdx.x;
    if (idx >= N * 10) return;
    int r = idx / 10, c = idx - r * 10;
    float dv = g_dinv[r];
    float4 a = ((const float4*)g_agg2)[idx];
    float4 b = ((const float4*)b2)[c];
    float4 o;
    o.x = fmaf(a.x, dv, b.x);
    o.y = fmaf(a.y, dv, b.y);
    o.z = fmaf(a.z, dv, b.z);
    o.w = fmaf(a.w, dv, b.w);
    out[idx] = o;
}

extern "C" void kernel_launch(void* const* d_in, const int* in_sizes, int n_in,
                              void* d_out, int out_size) {
    const float* x  = (const float*)d_in[0];
    const void*  ei = (const void*)d_in[1];
    const float* W1 = (const float*)d_in[2];
    const float* b1 = (const float*)d_in[3];
    const float* W2 = (const float*)d_in[4];
    const float* b2 = (const float*)d_in[5];

    int N = in_sizes[0] / FDIM;     // 50000
    int E = in_sizes[1] / 2;        // 800000

    void* degp = nullptr;
    cudaGetSymbolAddress(&degp, g_deg);
    cudaMemsetAsync(degp, 0, (size_t)N * sizeof(int));

    int smem1 = (128 * SXP + 64 * SWP) * sizeof(float);        // ~68 KB
    int smem2 = (128 * SX2P + 128 * SW2P) * sizeof(float);     // ~88 KB
    cudaFuncSetAttribute(gemm1_kernel, cudaFuncAttributeMaxDynamicSharedMemorySize, smem1);
    cudaFuncSetAttribute(gemm2_kernel, cudaFuncAttributeMaxDynamicSharedMemorySize, smem2);

    detect_kernel<<<1, 32>>>((const int*)ei);
    convert_kernel<<<(E + 255) / 256, 256>>>(ei, E);
    dinv_kernel<<<(N + 255) / 256, 256>>>(N);

    gemm1_kernel<<<(N + 127) / 128, 256, smem1>>>(x, W1, N);
    scatter1_kernel<<<(E + 7) / 8, 256>>>(E);

    gemm2_kernel<<<(N + 127) / 128, 256, smem2>>>(W2, (const float4*)x, b1, N);
    scatter2_kernel<<<(E * 10 + 255) / 256, 256>>>(E);
    final_kernel<<<(N * 10 + 255) / 256, 256>>>(b2, (float4*)d_out, N);
}